// round 10
// baseline (speedup 1.0000x reference)
#include <cuda_runtime.h>
#include <cuda_fp16.h>

#define C_DIM 2048
#define B_DIM 64
#define I_DIM 8
#define U_DIM 32
#define D_DIM 16
#define UD    512
#define NBLK  148
#define NTH   1024

typedef unsigned long long u64;
typedef unsigned int u32;

// ---- scratch (static __device__: allocation-free) ----
__device__ float g_xt[C_DIM * B_DIM * I_DIM];     // x transposed: [c][b][i]
__device__ float g_spart[NBLK * B_DIM * UD];      // per-block s partials
__device__ u32   g_vh[(B_DIM / 2) * UD];          // v as half2 pairs: [b/2][ud]
__device__ float g_b[C_DIM * U_DIM];              // routing logits

__device__ __forceinline__ u64 mul2(u64 a, u64 b) {
    u64 r; asm("mul.rn.f32x2 %0, %1, %2;" : "=l"(r) : "l"(a), "l"(b)); return r;
}
__device__ __forceinline__ u64 fma2(u64 a, u64 b, u64 c) {
    u64 r; asm("fma.rn.f32x2 %0, %1, %2, %3;" : "=l"(r) : "l"(a), "l"(b), "l"(c)); return r;
}
__device__ __forceinline__ float hadd2(u64 a) {
    float lo, hi; asm("mov.b64 {%0,%1}, %2;" : "=f"(lo), "=f"(hi) : "l"(a));
    return lo + hi;
}
__device__ __forceinline__ u32 ldg_u32(const u32* p) {
    u32 r; asm volatile("ld.global.nc.b32 %0, [%1];" : "=r"(r) : "l"(p)); return r;
}
__device__ __forceinline__ u32 smem_u32(const void* p) {
    return (u32)__cvta_generic_to_shared(p);
}
__device__ __forceinline__ void cp16(u32 dst, const void* src) {
    asm volatile("cp.async.cg.shared.global [%0], [%1], 16;" :: "r"(dst), "l"(src));
}
#define CP_COMMIT() asm volatile("cp.async.commit_group;")
#define CP_WAIT0()  asm volatile("cp.async.wait_group 0;" ::: "memory")
__device__ __forceinline__ void lds_2u64(u32 a, u64& x, u64& y) {
    asm("ld.shared.v2.u64 {%0,%1}, [%2];" : "=l"(x), "=l"(y) : "r"(a));
}
__device__ __forceinline__ void lds_2u64v(u32 a, u64& x, u64& y) {
    asm volatile("ld.shared.v2.u64 {%0,%1}, [%2];" : "=l"(x), "=l"(y) : "r"(a));
}
__device__ __forceinline__ float dot8(u64 wa0, u64 wa1, u64 wb0, u64 wb1,
                                      u64 x0, u64 x1, u64 x2, u64 x3) {
    u64 acc = mul2(wa0, x0);
    acc = fma2(wa1, x1, acc);
    acc = fma2(wb0, x2, acc);
    acc = fma2(wb1, x3, acc);
    return hadd2(acc);
}

// x (B,I,C) -> g_xt[c][b][i]
__global__ void k_transpose(const float* __restrict__ x) {
    int idx = blockIdx.x * blockDim.x + threadIdx.x;
    if (idx >= C_DIM * B_DIM * I_DIM) return;
    int c = idx >> 9;
    int r = idx & 511;
    int b = r >> 3;
    int i = r & 7;
    g_xt[idx] = x[(b * I_DIM + i) * C_DIM + c];
}

// ---------------------------------------------------------------------------
// Fused routing pass, cp.async software-pipelined.
// 32 warps = 16 ud-groups (wu) x 2 b-groups (wb); lane owns ud = wu*32+lane,
// batches b = wb*32 + 0..31.
// W staged SWIZZLED: [ihalf][ud] 16B chunks -> conflict-free lane reads.
// v read as half2 pairs (b even/odd), stash as packed half2 x2 (STS.64).
// ---------------------------------------------------------------------------
template <int PASS>
__global__ void __launch_bounds__(NTH, 1) k_pass(const float* __restrict__ W) {
    extern __shared__ char dyn[];
    // layout: Wbuf[2][16384] | xbuf[2][2048] | stash[65536 (PASS>0)]
    const u32 wbase  = smem_u32(dyn);
    const u32 xbase  = wbase + 32768;
    const u32 stbase = xbase + 4096;
    __shared__ float red_sm[2][2][32];

    const int tid  = threadIdx.x;
    const int w    = tid >> 5;
    const int lane = tid & 31;
    const int wu   = w & 15;
    const int wb   = w >> 4;
    const int hw   = lane >> 4;
    const int ud   = wu * 32 + lane;

    // swizzled W staging dst for this thread's chunk (tid = ud*2 + ihalf)
    const u32 wdst = (u32)((tid & 1) * 8192 + (tid >> 1) * 16);

    float sacc[32];
#pragma unroll
    for (int r = 0; r < 32; r++) sacc[r] = 0.f;

    const int cbeg = (blockIdx.x * C_DIM) / NBLK;
    const int cend = ((blockIdx.x + 1) * C_DIM) / NBLK;
    int par = 0;

    // prologue: stage first c
    cp16(wbase + wdst, (const char*)(W + (size_t)cbeg * 4096) + tid * 16);
    if (tid < 128)
        cp16(xbase + tid * 16, (const char*)(g_xt + cbeg * 512) + tid * 16);
    CP_COMMIT();
    CP_WAIT0();
    __syncthreads();

    for (int c = cbeg; c < cend; c++) {
        // issue next c's staging into the other buffer (overlaps phase A)
        if (c + 1 < cend) {
            const int np = par ^ 1;
            cp16(wbase + np * 16384 + wdst,
                 (const char*)(W + (size_t)(c + 1) * 4096) + tid * 16);
            if (tid < 128)
                cp16(xbase + np * 2048 + tid * 16,
                     (const char*)(g_xt + (c + 1) * 512) + tid * 16);
        }
        CP_COMMIT();

        // this lane's W row from swizzled smem (conflict-free 16B-stride)
        u64 wa0, wa1, wbb0, wbb1;
        lds_2u64(wbase + par * 16384 + ud * 16, wa0, wa1);
        lds_2u64(wbase + par * 16384 + 8192 + ud * 16, wbb0, wbb1);

        float bprev = (PASS == 2) ? g_b[c * U_DIM + lane] : 0.f;
        const u32* vb = g_vh + (wb * 16) * UD + ud;       // half2 per 2 batches
        const u32 xb = xbase + par * 2048 + wb * 1024;
        float dp = 0.f;

#pragma unroll
        for (int j = 0; j < 8; j++) {           // 4 batches per chunk
            u32 pk[2];
#pragma unroll
            for (int t2 = 0; t2 < 2; t2++) {    // 2 batches per step
                const int r = j * 4 + t2 * 2;
                u64 x0, x1, x2, x3, y0, y1, y2, y3;
                lds_2u64v(xb + r * 32,      x0, x1);
                lds_2u64v(xb + r * 32 + 16, x2, x3);
                lds_2u64v(xb + r * 32 + 32, y0, y1);
                lds_2u64v(xb + r * 32 + 48, y2, y3);
                float ua = dot8(wa0, wa1, wbb0, wbb1, x0, x1, x2, x3);
                float ub = dot8(wa0, wa1, wbb0, wbb1, y0, y1, y2, y3);
                if (PASS > 0) {
                    u32 vh = ldg_u32(vb + (r >> 1) * UD);        // coalesced
                    float2 vv = __half22float2(*(__half2*)&vh);
                    dp = fmaf(ua, vv.x, dp);
                    dp = fmaf(ub, vv.y, dp);
                    __half2 h2 = __floats2half2_rn(ua, ub);
                    pk[t2] = *(u32*)&h2;
                } else {
                    sacc[r]     += ua;
                    sacc[r + 1] += ub;
                }
            }
            if (PASS > 0) {
                asm volatile("st.shared.v2.b32 [%0], {%1,%2};"
                             :: "r"(stbase + (j * NTH + tid) * 8),
                                "r"(pk[0]), "r"(pk[1]));
            }
        }

        if (PASS > 0) {
            // reduce dp over d (16-lane segments); lanes 0/16 hold u partials
#pragma unroll
            for (int off = 8; off; off >>= 1)
                dp += __shfl_down_sync(0xffffffffu, dp, off, 16);
            if ((lane & 15) == 0)
                red_sm[par][wb][wu * 2 + hw] = dp;
        }

        CP_WAIT0();                 // next c's operands landed
        __syncthreads();            // the ONLY barrier this c

        if (PASS > 0) {
            // redundant per-warp softmax over u (lane = u)
            float dv = red_sm[par][0][lane] + red_sm[par][1][lane];
            float bv = dv * (1.0f / 64.0f) + bprev;
            if (PASS == 1 && w == 0) g_b[c * U_DIM + lane] = bv;
            float m = bv;
#pragma unroll
            for (int off = 16; off; off >>= 1)
                m = fmaxf(m, __shfl_xor_sync(0xffffffffu, m, off));
            float e = __expf(bv - m);
            float ssum = e;
#pragma unroll
            for (int off = 16; off; off >>= 1)
                ssum += __shfl_xor_sync(0xffffffffu, ssum, off);
            float cij = __shfl_sync(0xffffffffu, e / ssum, wu * 2 + hw);

            // phase B: accumulate s from stash (self-written, no extra sync)
#pragma unroll
            for (int j = 0; j < 8; j++) {
                u32 q0, q1;
                asm volatile("ld.shared.v2.b32 {%0,%1}, [%2];"
                             : "=r"(q0), "=r"(q1)
                             : "r"(stbase + (j * NTH + tid) * 8));
                float2 a = __half22float2(*(__half2*)&q0);
                float2 bq = __half22float2(*(__half2*)&q1);
                sacc[j * 4]     = fmaf(cij, a.x,  sacc[j * 4]);
                sacc[j * 4 + 1] = fmaf(cij, a.y,  sacc[j * 4 + 1]);
                sacc[j * 4 + 2] = fmaf(cij, bq.x, sacc[j * 4 + 2]);
                sacc[j * 4 + 3] = fmaf(cij, bq.y, sacc[j * 4 + 3]);
            }
        }
        par ^= 1;
    }

    const float scale = (PASS == 0) ? (1.0f / 32.0f) : 1.0f;
    float* sp = g_spart + (size_t)blockIdx.x * (B_DIM * UD) + ud;
#pragma unroll
    for (int r = 0; r < 32; r++)
        sp[(wb * 32 + r) * UD] = sacc[r] * scale;
}

// Reduce per-block s partials, apply squash (mag over U axis — reference quirk).
// 1024 threads: two partial-halves per ud, then combine.
__global__ void k_redsquash(float* __restrict__ dout, int final_out) {
    __shared__ float part[UD];
    __shared__ float sq_sm[UD];
    __shared__ float r_sm[D_DIM];
    const int b  = blockIdx.x;
    const int ud = threadIdx.x & 511;
    const int ph = threadIdx.x >> 9;
    float val = 0.f;
    const float* sp = g_spart + b * UD + ud;
    const int p0 = ph * 74;
#pragma unroll 4
    for (int p = p0; p < p0 + 74; p++) val += sp[(size_t)p * (B_DIM * UD)];
    if (ph) part[ud] = val;
    __syncthreads();
    if (!ph) {
        val += part[ud];
        sq_sm[ud] = val * val;
    }
    __syncthreads();
    if (threadIdx.x < D_DIM) {
        float msq = 0.f;
#pragma unroll
        for (int u = 0; u < U_DIM; u++) msq += sq_sm[u * D_DIM + threadIdx.x];
        r_sm[threadIdx.x] = sqrtf(msq) / (1.0f + msq);   // mag_sq/((1+mag_sq)*mag)
    }
    __syncthreads();
    if (!ph) {
        float v = val * r_sm[ud & 15];
        if (final_out) {
            dout[b * UD + ud] = v;
        } else {
            // store v as half into paired layout g_vh[b/2][ud] (lo=even b, hi=odd b)
            ((__half*)g_vh)[(b >> 1) * (UD * 2) + ud * 2 + (b & 1)] = __float2half_rn(v);
        }
    }
}

extern "C" void kernel_launch(void* const* d_in, const int* in_sizes, int n_in,
                              void* d_out, int out_size) {
    const float* x = (const float*)d_in[0];
    const float* W = (const float*)d_in[1];
    if (n_in >= 2 && in_sizes[0] == C_DIM * U_DIM * D_DIM * I_DIM) {
        const float* t = x; x = W; W = t;
    }
    float* out = (float*)d_out;

    const int SM0 = 32768 + 4096;            // W/x buffers only
    const int SM1 = 32768 + 4096 + 65536;    // + stash
    cudaFuncSetAttribute(k_pass<0>, cudaFuncAttributeMaxDynamicSharedMemorySize, SM0);
    cudaFuncSetAttribute(k_pass<1>, cudaFuncAttributeMaxDynamicSharedMemorySize, SM1);
    cudaFuncSetAttribute(k_pass<2>, cudaFuncAttributeMaxDynamicSharedMemorySize, SM1);

    k_transpose<<<(C_DIM * B_DIM * I_DIM + 255) / 256, 256>>>(x);

    // iteration 1: uniform cij -> s1 -> v1
    k_pass<0><<<NBLK, NTH, SM0>>>(W);
    k_redsquash<<<B_DIM, NTH>>>(out, 0);

    // iteration 2: delta(v1), b = delta, softmax -> s2 -> v2
    k_pass<1><<<NBLK, NTH, SM1>>>(W);
    k_redsquash<<<B_DIM, NTH>>>(out, 0);

    // iteration 3: delta(v2), b += delta, softmax -> s3 -> v3 (output)
    k_pass<2><<<NBLK, NTH, SM1>>>(W);
    k_redsquash<<<B_DIM, NTH>>>(out, 1);
}

// round 11
// speedup vs baseline: 1.0204x; 1.0204x over previous
#include <cuda_runtime.h>
#include <cuda_fp16.h>

#define C_DIM 2048
#define B_DIM 64
#define I_DIM 8
#define U_DIM 32
#define D_DIM 16
#define UD    512
#define NBLK  148
#define NTH   1024

typedef unsigned long long u64;
typedef unsigned int u32;

// ---- scratch (static __device__: allocation-free) ----
__device__ float g_xt[C_DIM * B_DIM * I_DIM];     // x transposed: [c][b][i]
__device__ float g_spart[NBLK * B_DIM * UD];      // per-block s partials
__device__ u32   g_vh[(B_DIM / 2) * UD];          // v as half2 pairs: [b/2][ud]
__device__ float g_b[C_DIM * U_DIM];              // routing logits

__device__ __forceinline__ u64 mul2(u64 a, u64 b) {
    u64 r; asm("mul.rn.f32x2 %0, %1, %2;" : "=l"(r) : "l"(a), "l"(b)); return r;
}
__device__ __forceinline__ u64 fma2(u64 a, u64 b, u64 c) {
    u64 r; asm("fma.rn.f32x2 %0, %1, %2, %3;" : "=l"(r) : "l"(a), "l"(b), "l"(c)); return r;
}
__device__ __forceinline__ float hadd2(u64 a) {
    float lo, hi; asm("mov.b64 {%0,%1}, %2;" : "=f"(lo), "=f"(hi) : "l"(a));
    return lo + hi;
}
__device__ __forceinline__ u32 ldg_u32(const u32* p) {
    u32 r; asm volatile("ld.global.nc.b32 %0, [%1];" : "=r"(r) : "l"(p)); return r;
}
__device__ __forceinline__ u32 smem_u32(const void* p) {
    return (u32)__cvta_generic_to_shared(p);
}
__device__ __forceinline__ void cp16(u32 dst, const void* src) {
    asm volatile("cp.async.cg.shared.global [%0], [%1], 16;" :: "r"(dst), "l"(src));
}
#define CP_COMMIT() asm volatile("cp.async.commit_group;")
#define CP_WAIT0()  asm volatile("cp.async.wait_group 0;" ::: "memory")
__device__ __forceinline__ void lds_2u64(u32 a, u64& x, u64& y) {
    asm("ld.shared.v2.u64 {%0,%1}, [%2];" : "=l"(x), "=l"(y) : "r"(a));
}
__device__ __forceinline__ void lds_2u64v(u32 a, u64& x, u64& y) {
    asm volatile("ld.shared.v2.u64 {%0,%1}, [%2];" : "=l"(x), "=l"(y) : "r"(a));
}
__device__ __forceinline__ float dot8(u64 wa0, u64 wa1, u64 wb0, u64 wb1,
                                      u64 x0, u64 x1, u64 x2, u64 x3) {
    u64 acc = mul2(wa0, x0);
    acc = fma2(wa1, x1, acc);
    acc = fma2(wb0, x2, acc);
    acc = fma2(wb1, x3, acc);
    return hadd2(acc);
}

// x (B,I,C) -> g_xt[c][b][i]
__global__ void k_transpose(const float* __restrict__ x) {
    int idx = blockIdx.x * blockDim.x + threadIdx.x;
    if (idx >= C_DIM * B_DIM * I_DIM) return;
    int c = idx >> 9;
    int r = idx & 511;
    int b = r >> 3;
    int i = r & 7;
    g_xt[idx] = x[(b * I_DIM + i) * C_DIM + c];
}

// ---------------------------------------------------------------------------
// Fused routing pass, cp.async software-pipelined.
// 32 warps = 16 ud-groups (wu) x 2 b-groups (wb); lane owns ud = wu*32+lane,
// batches b = wb*32 + 0..31.
// W staged SWIZZLED: [ihalf][ud] 16B chunks -> conflict-free lane reads.
// v read as half2 pairs (b even/odd), stash as packed half2 x2 (STS.64).
// ---------------------------------------------------------------------------
template <int PASS>
__global__ void __launch_bounds__(NTH, 1) k_pass(const float* __restrict__ W) {
    extern __shared__ char dyn[];
    // layout: Wbuf[2][16384] | xbuf[2][2048] | stash[65536 (PASS>0)]
    const u32 wbase  = smem_u32(dyn);
    const u32 xbase  = wbase + 32768;
    const u32 stbase = xbase + 4096;
    __shared__ float red_sm[2][2][32];

    const int tid  = threadIdx.x;
    const int w    = tid >> 5;
    const int lane = tid & 31;
    const int wu   = w & 15;
    const int wb   = w >> 4;
    const int hw   = lane >> 4;
    const int ud   = wu * 32 + lane;

    // swizzled W staging dst for this thread's chunk (tid = ud*2 + ihalf)
    const u32 wdst = (u32)((tid & 1) * 8192 + (tid >> 1) * 16);

    float sacc[32];
#pragma unroll
    for (int r = 0; r < 32; r++) sacc[r] = 0.f;

    const int cbeg = (blockIdx.x * C_DIM) / NBLK;
    const int cend = ((blockIdx.x + 1) * C_DIM) / NBLK;
    int par = 0;

    // prologue: stage first c
    cp16(wbase + wdst, (const char*)(W + (size_t)cbeg * 4096) + tid * 16);
    if (tid < 128)
        cp16(xbase + tid * 16, (const char*)(g_xt + cbeg * 512) + tid * 16);
    CP_COMMIT();
    CP_WAIT0();
    __syncthreads();

    for (int c = cbeg; c < cend; c++) {
        // issue next c's staging into the other buffer (overlaps phase A)
        if (c + 1 < cend) {
            const int np = par ^ 1;
            cp16(wbase + np * 16384 + wdst,
                 (const char*)(W + (size_t)(c + 1) * 4096) + tid * 16);
            if (tid < 128)
                cp16(xbase + np * 2048 + tid * 16,
                     (const char*)(g_xt + (c + 1) * 512) + tid * 16);
        }
        CP_COMMIT();

        // this lane's W row from swizzled smem (conflict-free 16B-stride)
        u64 wa0, wa1, wbb0, wbb1;
        lds_2u64(wbase + par * 16384 + ud * 16, wa0, wa1);
        lds_2u64(wbase + par * 16384 + 8192 + ud * 16, wbb0, wbb1);

        float bprev = (PASS == 2) ? g_b[c * U_DIM + lane] : 0.f;
        const u32* vb = g_vh + (wb * 16) * UD + ud;       // half2 per 2 batches
        const u32 xb = xbase + par * 2048 + wb * 1024;
        float dp = 0.f;

#pragma unroll
        for (int j = 0; j < 8; j++) {           // 4 batches per chunk
            u32 pk[2];
#pragma unroll
            for (int t2 = 0; t2 < 2; t2++) {    // 2 batches per step
                const int r = j * 4 + t2 * 2;
                u64 x0, x1, x2, x3, y0, y1, y2, y3;
                lds_2u64v(xb + r * 32,      x0, x1);
                lds_2u64v(xb + r * 32 + 16, x2, x3);
                lds_2u64v(xb + r * 32 + 32, y0, y1);
                lds_2u64v(xb + r * 32 + 48, y2, y3);
                float ua = dot8(wa0, wa1, wbb0, wbb1, x0, x1, x2, x3);
                float ub = dot8(wa0, wa1, wbb0, wbb1, y0, y1, y2, y3);
                if (PASS > 0) {
                    u32 vh = ldg_u32(vb + (r >> 1) * UD);        // coalesced
                    float2 vv = __half22float2(*(__half2*)&vh);
                    dp = fmaf(ua, vv.x, dp);
                    dp = fmaf(ub, vv.y, dp);
                    __half2 h2 = __floats2half2_rn(ua, ub);
                    pk[t2] = *(u32*)&h2;
                } else {
                    sacc[r]     += ua;
                    sacc[r + 1] += ub;
                }
            }
            if (PASS > 0) {
                asm volatile("st.shared.v2.b32 [%0], {%1,%2};"
                             :: "r"(stbase + (j * NTH + tid) * 8),
                                "r"(pk[0]), "r"(pk[1]));
            }
        }

        if (PASS > 0) {
            // reduce dp over d (16-lane segments); lanes 0/16 hold u partials
#pragma unroll
            for (int off = 8; off; off >>= 1)
                dp += __shfl_down_sync(0xffffffffu, dp, off, 16);
            if ((lane & 15) == 0)
                red_sm[par][wb][wu * 2 + hw] = dp;
        }

        CP_WAIT0();                 // next c's operands landed
        __syncthreads();            // the ONLY barrier this c

        if (PASS > 0) {
            // redundant per-warp softmax over u (lane = u)
            float dv = red_sm[par][0][lane] + red_sm[par][1][lane];
            float bv = dv * (1.0f / 64.0f) + bprev;
            if (PASS == 1 && w == 0) g_b[c * U_DIM + lane] = bv;
            float m = bv;
#pragma unroll
            for (int off = 16; off; off >>= 1)
                m = fmaxf(m, __shfl_xor_sync(0xffffffffu, m, off));
            float e = __expf(bv - m);
            float ssum = e;
#pragma unroll
            for (int off = 16; off; off >>= 1)
                ssum += __shfl_xor_sync(0xffffffffu, ssum, off);
            float cij = __shfl_sync(0xffffffffu, e / ssum, wu * 2 + hw);

            // phase B: accumulate s from stash (self-written, no extra sync)
#pragma unroll
            for (int j = 0; j < 8; j++) {
                u32 q0, q1;
                asm volatile("ld.shared.v2.b32 {%0,%1}, [%2];"
                             : "=r"(q0), "=r"(q1)
                             : "r"(stbase + (j * NTH + tid) * 8));
                float2 a = __half22float2(*(__half2*)&q0);
                float2 bq = __half22float2(*(__half2*)&q1);
                sacc[j * 4]     = fmaf(cij, a.x,  sacc[j * 4]);
                sacc[j * 4 + 1] = fmaf(cij, a.y,  sacc[j * 4 + 1]);
                sacc[j * 4 + 2] = fmaf(cij, bq.x, sacc[j * 4 + 2]);
                sacc[j * 4 + 3] = fmaf(cij, bq.y, sacc[j * 4 + 3]);
            }
        }
        par ^= 1;
    }

    const float scale = (PASS == 0) ? (1.0f / 32.0f) : 1.0f;
    float* sp = g_spart + (size_t)blockIdx.x * (B_DIM * UD) + ud;
#pragma unroll
    for (int r = 0; r < 32; r++)
        sp[(wb * 32 + r) * UD] = sacc[r] * scale;
}

// Reduce per-block s partials, apply squash (mag over U axis — reference quirk).
// 1024 threads: two partial-halves per ud, then combine.
__global__ void k_redsquash(float* __restrict__ dout, int final_out) {
    __shared__ float part[UD];
    __shared__ float sq_sm[UD];
    __shared__ float r_sm[D_DIM];
    const int b  = blockIdx.x;
    const int ud = threadIdx.x & 511;
    const int ph = threadIdx.x >> 9;
    float val = 0.f;
    const float* sp = g_spart + b * UD + ud;
    const int p0 = ph * 74;
#pragma unroll 4
    for (int p = p0; p < p0 + 74; p++) val += sp[(size_t)p * (B_DIM * UD)];
    if (ph) part[ud] = val;
    __syncthreads();
    if (!ph) {
        val += part[ud];
        sq_sm[ud] = val * val;
    }
    __syncthreads();
    if (threadIdx.x < D_DIM) {
        float msq = 0.f;
#pragma unroll
        for (int u = 0; u < U_DIM; u++) msq += sq_sm[u * D_DIM + threadIdx.x];
        r_sm[threadIdx.x] = sqrtf(msq) / (1.0f + msq);   // mag_sq/((1+mag_sq)*mag)
    }
    __syncthreads();
    if (!ph) {
        float v = val * r_sm[ud & 15];
        if (final_out) {
            dout[b * UD + ud] = v;
        } else {
            // store v as half into paired layout g_vh[b/2][ud] (lo=even b, hi=odd b)
            ((__half*)g_vh)[(b >> 1) * (UD * 2) + ud * 2 + (b & 1)] = __float2half_rn(v);
        }
    }
}

extern "C" void kernel_launch(void* const* d_in, const int* in_sizes, int n_in,
                              void* d_out, int out_size) {
    const float* x = (const float*)d_in[0];
    const float* W = (const float*)d_in[1];
    if (n_in >= 2 && in_sizes[0] == C_DIM * U_DIM * D_DIM * I_DIM) {
        const float* t = x; x = W; W = t;
    }
    float* out = (float*)d_out;

    const int SM0 = 32768 + 4096;            // W/x buffers only
    const int SM1 = 32768 + 4096 + 65536;    // + stash
    cudaFuncSetAttribute(k_pass<0>, cudaFuncAttributeMaxDynamicSharedMemorySize, SM0);
    cudaFuncSetAttribute(k_pass<1>, cudaFuncAttributeMaxDynamicSharedMemorySize, SM1);
    cudaFuncSetAttribute(k_pass<2>, cudaFuncAttributeMaxDynamicSharedMemorySize, SM1);

    k_transpose<<<(C_DIM * B_DIM * I_DIM + 255) / 256, 256>>>(x);

    // iteration 1: uniform cij -> s1 -> v1
    k_pass<0><<<NBLK, NTH, SM0>>>(W);
    k_redsquash<<<B_DIM, NTH>>>(out, 0);

    // iteration 2: delta(v1), b = delta, softmax -> s2 -> v2
    k_pass<1><<<NBLK, NTH, SM1>>>(W);
    k_redsquash<<<B_DIM, NTH>>>(out, 0);

    // iteration 3: delta(v2), b += delta, softmax -> s3 -> v3 (output)
    k_pass<2><<<NBLK, NTH, SM1>>>(W);
    k_redsquash<<<B_DIM, NTH>>>(out, 1);
}

// round 12
// speedup vs baseline: 1.1910x; 1.1672x over previous
#include <cuda_runtime.h>
#include <cuda_fp16.h>

#define C_DIM 2048
#define B_DIM 64
#define I_DIM 8
#define U_DIM 32
#define D_DIM 16
#define UD    512
#define NBLK  148
#define NTH   1024

typedef unsigned long long u64;
typedef unsigned int u32;

// ---- scratch (static __device__: allocation-free) ----
__device__ float g_xt[C_DIM * B_DIM * I_DIM];       // x transposed: [c][b][i]
__device__ float g_spart[NBLK * B_DIM * UD];        // per-block s partials
__device__ u32   g_vh[(B_DIM / 2) * UD];            // v half2 pairs: [b/2][ud]
__device__ float g_b[C_DIM * U_DIM];                // routing logits
__device__ u32   g_uh[C_DIM * (B_DIM / 2) * UD];    // u_hat half2: [c][b/2][ud] (128 MB)

__device__ __forceinline__ u64 mul2(u64 a, u64 b) {
    u64 r; asm("mul.rn.f32x2 %0, %1, %2;" : "=l"(r) : "l"(a), "l"(b)); return r;
}
__device__ __forceinline__ u64 fma2(u64 a, u64 b, u64 c) {
    u64 r; asm("fma.rn.f32x2 %0, %1, %2, %3;" : "=l"(r) : "l"(a), "l"(b), "l"(c)); return r;
}
__device__ __forceinline__ float hadd2(u64 a) {
    float lo, hi; asm("mov.b64 {%0,%1}, %2;" : "=f"(lo), "=f"(hi) : "l"(a));
    return lo + hi;
}
__device__ __forceinline__ u32 ldg_u32(const u32* p) {
    u32 r; asm volatile("ld.global.nc.b32 %0, [%1];" : "=r"(r) : "l"(p)); return r;
}
__device__ __forceinline__ u32 smem_u32(const void* p) {
    return (u32)__cvta_generic_to_shared(p);
}
__device__ __forceinline__ void cp16(u32 dst, const void* src) {
    asm volatile("cp.async.cg.shared.global [%0], [%1], 16;" :: "r"(dst), "l"(src));
}
#define CP_COMMIT() asm volatile("cp.async.commit_group;")
#define CP_WAIT0()  asm volatile("cp.async.wait_group 0;" ::: "memory")
__device__ __forceinline__ void lds_2u64(u32 a, u64& x, u64& y) {
    asm("ld.shared.v2.u64 {%0,%1}, [%2];" : "=l"(x), "=l"(y) : "r"(a));
}
__device__ __forceinline__ void lds_2u64v(u32 a, u64& x, u64& y) {
    asm volatile("ld.shared.v2.u64 {%0,%1}, [%2];" : "=l"(x), "=l"(y) : "r"(a));
}
__device__ __forceinline__ u32 lds_u32(u32 a) {
    u32 r; asm volatile("ld.shared.b32 %0, [%1];" : "=r"(r) : "r"(a)); return r;
}
__device__ __forceinline__ float dot8(u64 wa0, u64 wa1, u64 wb0, u64 wb1,
                                      u64 x0, u64 x1, u64 x2, u64 x3) {
    u64 acc = mul2(wa0, x0);
    acc = fma2(wa1, x1, acc);
    acc = fma2(wb0, x2, acc);
    acc = fma2(wb1, x3, acc);
    return hadd2(acc);
}

// x (B,I,C) -> g_xt[c][b][i]
__global__ void k_transpose(const float* __restrict__ x) {
    int idx = blockIdx.x * blockDim.x + threadIdx.x;
    if (idx >= C_DIM * B_DIM * I_DIM) return;
    int c = idx >> 9;
    int r = idx & 511;
    int b = r >> 3;
    int i = r & 7;
    g_xt[idx] = x[(b * I_DIM + i) * C_DIM + c];
}

// ---------------------------------------------------------------------------
// p0: einsum -> u_hat (fp16, gmem) + s1 partials (uniform cij = 1/32).
// 32 warps = 16 ud-groups (wu) x 2 b-groups (wb); lane owns ud = wu*32+lane,
// batches b = wb*32 + 0..31. W staged swizzled ([ihalf][ud] 16B chunks).
// ---------------------------------------------------------------------------
__global__ void __launch_bounds__(NTH, 1) k_einsum(const float* __restrict__ W) {
    extern __shared__ char dyn[];
    const u32 wbase = smem_u32(dyn);          // Wbuf[2][16384]
    const u32 xbase = wbase + 32768;          // xbuf[2][2048]

    const int tid  = threadIdx.x;
    const int w    = tid >> 5;
    const int lane = tid & 31;
    const int wu   = w & 15;
    const int wb   = w >> 4;
    const int ud   = wu * 32 + lane;
    const u32 wdst = (u32)((tid & 1) * 8192 + (tid >> 1) * 16);

    float sacc[32];
#pragma unroll
    for (int r = 0; r < 32; r++) sacc[r] = 0.f;

    const int cbeg = (blockIdx.x * C_DIM) / NBLK;
    const int cend = ((blockIdx.x + 1) * C_DIM) / NBLK;
    int par = 0;

    cp16(wbase + wdst, (const char*)(W + (size_t)cbeg * 4096) + tid * 16);
    if (tid < 128)
        cp16(xbase + tid * 16, (const char*)(g_xt + cbeg * 512) + tid * 16);
    CP_COMMIT();
    CP_WAIT0();
    __syncthreads();

    for (int c = cbeg; c < cend; c++) {
        if (c + 1 < cend) {
            const int np = par ^ 1;
            cp16(wbase + np * 16384 + wdst,
                 (const char*)(W + (size_t)(c + 1) * 4096) + tid * 16);
            if (tid < 128)
                cp16(xbase + np * 2048 + tid * 16,
                     (const char*)(g_xt + (c + 1) * 512) + tid * 16);
        }
        CP_COMMIT();

        u64 wa0, wa1, wbb0, wbb1;
        lds_2u64(wbase + par * 16384 + ud * 16, wa0, wa1);
        lds_2u64(wbase + par * 16384 + 8192 + ud * 16, wbb0, wbb1);

        const u32 xb = xbase + par * 2048 + wb * 1024;
        u32* uout = g_uh + (size_t)c * 16384 + (wb * 16) * 512 + ud;

#pragma unroll
        for (int t = 0; t < 16; t++) {        // batch pair t -> b = wb*32+2t, +1
            u64 x0, x1, x2, x3, y0, y1, y2, y3;
            lds_2u64v(xb + t * 64,      x0, x1);
            lds_2u64v(xb + t * 64 + 16, x2, x3);
            lds_2u64v(xb + t * 64 + 32, y0, y1);
            lds_2u64v(xb + t * 64 + 48, y2, y3);
            float ua = dot8(wa0, wa1, wbb0, wbb1, x0, x1, x2, x3);
            float ub = dot8(wa0, wa1, wbb0, wbb1, y0, y1, y2, y3);
            sacc[2 * t]     += ua;
            sacc[2 * t + 1] += ub;
            __half2 h2 = __floats2half2_rn(ua, ub);
            uout[t * 512] = *(u32*)&h2;       // coalesced over lanes (ud)
        }

        CP_WAIT0();
        __syncthreads();
        par ^= 1;
    }

    float* sp = g_spart + (size_t)blockIdx.x * (B_DIM * UD) + ud;
#pragma unroll
    for (int r = 0; r < 32; r++)
        sp[(wb * 32 + r) * UD] = sacc[r] * (1.0f / 32.0f);
}

// ---------------------------------------------------------------------------
// p1/p2: pure routing pass streaming u_hat from gmem (no einsum).
// Per c: stage 64 KB u_hat tile (cp.async, double-buffered), dp = u.v ->
// softmax -> s += cij*u (re-read from the SAME smem tile). 2 barriers/c.
// ---------------------------------------------------------------------------
template <int PASS>
__global__ void __launch_bounds__(NTH, 1) k_route() {
    extern __shared__ char dyn[];
    const u32 ubase = smem_u32(dyn);          // ubuf[2][65536]
    __shared__ float red_sm[2][2][32];

    const int tid  = threadIdx.x;
    const int w    = tid >> 5;
    const int lane = tid & 31;
    const int wu   = w & 15;
    const int wb   = w >> 4;
    const int hw   = lane >> 4;
    const int ud   = wu * 32 + lane;

    float sacc[32];
#pragma unroll
    for (int r = 0; r < 32; r++) sacc[r] = 0.f;

    const int cbeg = (blockIdx.x * C_DIM) / NBLK;
    const int cend = ((blockIdx.x + 1) * C_DIM) / NBLK;
    int par = 0;

    // prologue: stage first tile (4 x 16B per thread)
    {
        const char* src = (const char*)(g_uh + (size_t)cbeg * 16384);
#pragma unroll
        for (int k = 0; k < 4; k++)
            cp16(ubase + k * 16384 + tid * 16, src + k * 16384 + tid * 16);
        CP_COMMIT();
        CP_WAIT0();
        __syncthreads();
    }

    for (int c = cbeg; c < cend; c++) {
        if (c + 1 < cend) {
            const int np = par ^ 1;
            const char* src = (const char*)(g_uh + (size_t)(c + 1) * 16384);
#pragma unroll
            for (int k = 0; k < 4; k++)
                cp16(ubase + np * 65536 + k * 16384 + tid * 16,
                     src + k * 16384 + tid * 16);
        }
        CP_COMMIT();

        float bprev = (PASS == 2) ? g_b[c * U_DIM + lane] : 0.f;
        const u32 ub0 = ubase + par * 65536 + ((wb * 16) * 512 + ud) * 4;
        const u32* vb = g_vh + (wb * 16) * 512 + ud;
        float dp = 0.f;

#pragma unroll
        for (int t = 0; t < 16; t++) {
            u32 uh = lds_u32(ub0 + t * 2048);
            u32 vh = ldg_u32(vb + t * 512);
            float2 uu = __half22float2(*(__half2*)&uh);
            float2 vv = __half22float2(*(__half2*)&vh);
            dp = fmaf(uu.x, vv.x, dp);
            dp = fmaf(uu.y, vv.y, dp);
        }

        // reduce dp over d (16-lane segments); lanes 0/16 hold u partials
#pragma unroll
        for (int off = 8; off; off >>= 1)
            dp += __shfl_down_sync(0xffffffffu, dp, off, 16);
        if ((lane & 15) == 0)
            red_sm[par][wb][wu * 2 + hw] = dp;

        __syncthreads();                       // (1) red_sm ready

        // redundant per-warp softmax over u (lane = u)
        float dv = red_sm[par][0][lane] + red_sm[par][1][lane];
        float bv = dv * (1.0f / 64.0f) + bprev;
        if (PASS == 1 && w == 0) g_b[c * U_DIM + lane] = bv;
        float m = bv;
#pragma unroll
        for (int off = 16; off; off >>= 1)
            m = fmaxf(m, __shfl_xor_sync(0xffffffffu, m, off));
        float e = __expf(bv - m);
        float ssum = e;
#pragma unroll
        for (int off = 16; off; off >>= 1)
            ssum += __shfl_xor_sync(0xffffffffu, ssum, off);
        float cij = __shfl_sync(0xffffffffu, e / ssum, wu * 2 + hw);

        // phase B: s += cij * u_hat (re-read the smem tile)
#pragma unroll
        for (int t = 0; t < 16; t++) {
            u32 uh = lds_u32(ub0 + t * 2048);
            float2 uu = __half22float2(*(__half2*)&uh);
            sacc[2 * t]     = fmaf(cij, uu.x, sacc[2 * t]);
            sacc[2 * t + 1] = fmaf(cij, uu.y, sacc[2 * t + 1]);
        }

        CP_WAIT0();                            // next tile landed
        __syncthreads();                       // (2) tile[par] free for reuse
        par ^= 1;
    }

    float* sp = g_spart + (size_t)blockIdx.x * (B_DIM * UD) + ud;
#pragma unroll
    for (int r = 0; r < 32; r++)
        sp[(wb * 32 + r) * UD] = sacc[r];
}

// Reduce per-block s partials, apply squash (mag over U axis — reference quirk).
__global__ void k_redsquash(float* __restrict__ dout, int final_out) {
    __shared__ float part[UD];
    __shared__ float sq_sm[UD];
    __shared__ float r_sm[D_DIM];
    const int b  = blockIdx.x;
    const int ud = threadIdx.x & 511;
    const int ph = threadIdx.x >> 9;
    float val = 0.f;
    const float* sp = g_spart + b * UD + ud;
    const int p0 = ph * 74;
#pragma unroll 4
    for (int p = p0; p < p0 + 74; p++) val += sp[(size_t)p * (B_DIM * UD)];
    if (ph) part[ud] = val;
    __syncthreads();
    if (!ph) {
        val += part[ud];
        sq_sm[ud] = val * val;
    }
    __syncthreads();
    if (threadIdx.x < D_DIM) {
        float msq = 0.f;
#pragma unroll
        for (int u = 0; u < U_DIM; u++) msq += sq_sm[u * D_DIM + threadIdx.x];
        r_sm[threadIdx.x] = sqrtf(msq) / (1.0f + msq);   // mag_sq/((1+mag_sq)*mag)
    }
    __syncthreads();
    if (!ph) {
        float v = val * r_sm[ud & 15];
        if (final_out) {
            dout[b * UD + ud] = v;
        } else {
            // v as half in paired layout g_vh[b/2][ud] (lo=even b, hi=odd b)
            ((__half*)g_vh)[(b >> 1) * (UD * 2) + ud * 2 + (b & 1)] = __float2half_rn(v);
        }
    }
}

extern "C" void kernel_launch(void* const* d_in, const int* in_sizes, int n_in,
                              void* d_out, int out_size) {
    const float* x = (const float*)d_in[0];
    const float* W = (const float*)d_in[1];
    if (n_in >= 2 && in_sizes[0] == C_DIM * U_DIM * D_DIM * I_DIM) {
        const float* t = x; x = W; W = t;
    }
    float* out = (float*)d_out;

    const int SM0 = 32768 + 4096;     // k_einsum: W/x buffers
    const int SM1 = 2 * 65536;        // k_route: u_hat double buffer
    cudaFuncSetAttribute(k_einsum,   cudaFuncAttributeMaxDynamicSharedMemorySize, SM0);
    cudaFuncSetAttribute(k_route<1>, cudaFuncAttributeMaxDynamicSharedMemorySize, SM1);
    cudaFuncSetAttribute(k_route<2>, cudaFuncAttributeMaxDynamicSharedMemorySize, SM1);

    k_transpose<<<(C_DIM * B_DIM * I_DIM + 255) / 256, 256>>>(x);

    // iteration 1: einsum -> u_hat(fp16) + s1 -> v1
    k_einsum<<<NBLK, NTH, SM0>>>(W);
    k_redsquash<<<B_DIM, NTH>>>(out, 0);

    // iteration 2: stream u_hat: delta(v1), b = delta, softmax -> s2 -> v2
    k_route<1><<<NBLK, NTH, SM1>>>();
    k_redsquash<<<B_DIM, NTH>>>(out, 0);

    // iteration 3: stream u_hat: delta(v2), b += delta, softmax -> s3 -> v3
    k_route<2><<<NBLK, NTH, SM1>>>();
    k_redsquash<<<B_DIM, NTH>>>(out, 1);
}

// round 14
// speedup vs baseline: 1.2783x; 1.0733x over previous
#include <cuda_runtime.h>
#include <cuda_fp16.h>

#define C_DIM 2048
#define B_DIM 64
#define I_DIM 8
#define U_DIM 32
#define D_DIM 16
#define UD    512
#define NBLK  148
#define NTH   1024

typedef unsigned long long u64;
typedef unsigned int u32;

// ---- scratch (static __device__: allocation-free) ----
__device__ float g_xt[C_DIM * B_DIM * I_DIM];       // x transposed: [c][b][i]
__device__ float g_spart[NBLK * B_DIM * UD];        // per-block s partials
__device__ u32   g_vh[(B_DIM / 2) * UD];            // v half2 pairs: [b/2][ud]
__device__ float g_b[C_DIM * U_DIM];                // routing logits
__device__ u32   g_uh[C_DIM * (B_DIM / 2) * UD];    // u_hat half2: [c][b/2][ud] (128 MB)

__device__ __forceinline__ u64 mul2(u64 a, u64 b) {
    u64 r; asm("mul.rn.f32x2 %0, %1, %2;" : "=l"(r) : "l"(a), "l"(b)); return r;
}
__device__ __forceinline__ u64 fma2(u64 a, u64 b, u64 c) {
    u64 r; asm("fma.rn.f32x2 %0, %1, %2, %3;" : "=l"(r) : "l"(a), "l"(b), "l"(c)); return r;
}
__device__ __forceinline__ float hadd2(u64 a) {
    float lo, hi; asm("mov.b64 {%0,%1}, %2;" : "=f"(lo), "=f"(hi) : "l"(a));
    return lo + hi;
}
__device__ __forceinline__ u32 ldg_u32(const u32* p) {
    u32 r; asm volatile("ld.global.nc.b32 %0, [%1];" : "=r"(r) : "l"(p)); return r;
}
__device__ __forceinline__ u32 smem_u32(const void* p) {
    return (u32)__cvta_generic_to_shared(p);
}
__device__ __forceinline__ void lds_2u64(u32 a, u64& x, u64& y) {
    asm("ld.shared.v2.u64 {%0,%1}, [%2];" : "=l"(x), "=l"(y) : "r"(a));
}
__device__ __forceinline__ void lds_2u64v(u32 a, u64& x, u64& y) {
    asm volatile("ld.shared.v2.u64 {%0,%1}, [%2];" : "=l"(x), "=l"(y) : "r"(a));
}
__device__ __forceinline__ u32 lds_u32(u32 a) {
    u32 r; asm volatile("ld.shared.b32 %0, [%1];" : "=r"(r) : "r"(a)); return r;
}
__device__ __forceinline__ float dot8(u64 wa0, u64 wa1, u64 wb0, u64 wb1,
                                      u64 x0, u64 x1, u64 x2, u64 x3) {
    u64 acc = mul2(wa0, x0);
    acc = fma2(wa1, x1, acc);
    acc = fma2(wb0, x2, acc);
    acc = fma2(wb1, x3, acc);
    return hadd2(acc);
}

// ---- mbarrier + bulk-copy helpers ----
__device__ __forceinline__ void mbar_init(u32 a, u32 cnt) {
    asm volatile("mbarrier.init.shared.b64 [%0], %1;" :: "r"(a), "r"(cnt) : "memory");
}
__device__ __forceinline__ void fence_async() {
    asm volatile("fence.proxy.async.shared::cta;" ::: "memory");
}
__device__ __forceinline__ void mbar_expect(u32 a, u32 bytes) {
    asm volatile("mbarrier.arrive.expect_tx.shared.b64 _, [%0], %1;"
                 :: "r"(a), "r"(bytes) : "memory");
}
__device__ __forceinline__ void bulk_g2s(u32 dst, const void* src, u32 bytes, u32 mbar) {
    asm volatile("cp.async.bulk.shared::cta.global.mbarrier::complete_tx::bytes "
                 "[%0], [%1], %2, [%3];"
                 :: "r"(dst), "l"(src), "r"(bytes), "r"(mbar) : "memory");
}
__device__ __forceinline__ void mbar_wait(u32 a, u32 parity) {
    asm volatile(
        "{\n\t.reg .pred P;\n"
        "W_%=:\n\t"
        "mbarrier.try_wait.parity.shared.b64 P, [%0], %1;\n\t"
        "@!P bra W_%=;\n\t"
        "}" :: "r"(a), "r"(parity) : "memory");
}

// x (B,I,C) -> g_xt[c][b][i]
__global__ void k_transpose(const float* __restrict__ x) {
    int idx = blockIdx.x * blockDim.x + threadIdx.x;
    if (idx >= C_DIM * B_DIM * I_DIM) return;
    int c = idx >> 9;
    int r = idx & 511;
    int b = r >> 3;
    int i = r & 7;
    g_xt[idx] = x[(b * I_DIM + i) * C_DIM + c];
}

// ---------------------------------------------------------------------------
// p0: einsum -> u_hat (fp16, gmem) + s1 partials (uniform cij = 1/32).
// W_c (16 KB) + x_c (2 KB) double-buffered via ONE cp.async.bulk pair per c
// (no per-thread LDGSTS issue cost). W read linearly from smem.
// ---------------------------------------------------------------------------
__global__ void __launch_bounds__(NTH, 1) k_einsum(const float* __restrict__ W) {
    extern __shared__ char dyn[];
    const u32 wbase = smem_u32(dyn);          // Wbuf[2][16384]
    const u32 xbase = wbase + 32768;          // xbuf[2][2048]
    __shared__ u64 mbar_s;
    const u32 mb = smem_u32(&mbar_s);

    const int tid  = threadIdx.x;
    const int w    = tid >> 5;
    const int lane = tid & 31;
    const int wu   = w & 15;
    const int wb   = w >> 4;
    const int ud   = wu * 32 + lane;

    float sacc[32];
#pragma unroll
    for (int r = 0; r < 32; r++) sacc[r] = 0.f;

    const int cbeg = (blockIdx.x * C_DIM) / NBLK;
    const int cend = ((blockIdx.x + 1) * C_DIM) / NBLK;

    if (tid == 0) { mbar_init(mb, 1); fence_async(); }
    __syncthreads();
    if (tid == 0) {
        mbar_expect(mb, 18432);
        bulk_g2s(wbase, W + (size_t)cbeg * 4096, 16384, mb);
        bulk_g2s(xbase, g_xt + cbeg * 512, 2048, mb);
    }

    for (int c = cbeg; c < cend; c++) {
        const int idx = c - cbeg;
        const int par = idx & 1;
        mbar_wait(mb, idx & 1);          // data for c landed in buf[par]
        __syncthreads();                 // everyone done with buf[par^1]
        if (tid == 0 && c + 1 < cend) {
            mbar_expect(mb, 18432);
            bulk_g2s(wbase + (par ^ 1) * 16384, W + (size_t)(c + 1) * 4096, 16384, mb);
            bulk_g2s(xbase + (par ^ 1) * 2048, g_xt + (c + 1) * 512, 2048, mb);
        }

        u64 wa0, wa1, wbb0, wbb1;        // this lane's W row (linear layout)
        lds_2u64(wbase + par * 16384 + ud * 32, wa0, wa1);
        lds_2u64(wbase + par * 16384 + ud * 32 + 16, wbb0, wbb1);

        const u32 xb = xbase + par * 2048 + wb * 1024;
        u32* uout = g_uh + (size_t)c * 16384 + (wb * 16) * 512 + ud;

#pragma unroll
        for (int t = 0; t < 16; t++) {   // batch pair t -> b = wb*32+2t, +1
            u64 x0, x1, x2, x3, y0, y1, y2, y3;
            lds_2u64v(xb + t * 64,      x0, x1);
            lds_2u64v(xb + t * 64 + 16, x2, x3);
            lds_2u64v(xb + t * 64 + 32, y0, y1);
            lds_2u64v(xb + t * 64 + 48, y2, y3);
            float ua = dot8(wa0, wa1, wbb0, wbb1, x0, x1, x2, x3);
            float ub = dot8(wa0, wa1, wbb0, wbb1, y0, y1, y2, y3);
            sacc[2 * t]     += ua;
            sacc[2 * t + 1] += ub;
            __half2 h2 = __floats2half2_rn(ua, ub);
            uout[t * 512] = *(u32*)&h2;  // coalesced over lanes (ud)
        }
    }

    float* sp = g_spart + (size_t)blockIdx.x * (B_DIM * UD) + ud;
#pragma unroll
    for (int r = 0; r < 32; r++)
        sp[(wb * 32 + r) * UD] = sacc[r] * (1.0f / 32.0f);
}

// ---------------------------------------------------------------------------
// p1/p2: routing pass streaming u_hat. ONE 64 KB cp.async.bulk per c
// (double-buffered), dp = u.v -> softmax -> s += cij*u from the same tile.
// ---------------------------------------------------------------------------
template <int PASS>
__global__ void __launch_bounds__(NTH, 1) k_route() {
    extern __shared__ char dyn[];
    const u32 ubase = smem_u32(dyn);          // ubuf[2][65536]
    __shared__ float red_sm[2][32];
    __shared__ u64 mbar_s;
    const u32 mb = smem_u32(&mbar_s);

    const int tid  = threadIdx.x;
    const int w    = tid >> 5;
    const int lane = tid & 31;
    const int wu   = w & 15;
    const int wb   = w >> 4;
    const int hw   = lane >> 4;
    const int ud   = wu * 32 + lane;

    float sacc[32];
#pragma unroll
    for (int r = 0; r < 32; r++) sacc[r] = 0.f;

    const int cbeg = (blockIdx.x * C_DIM) / NBLK;
    const int cend = ((blockIdx.x + 1) * C_DIM) / NBLK;

    if (tid == 0) { mbar_init(mb, 1); fence_async(); }
    __syncthreads();
    if (tid == 0) {
        mbar_expect(mb, 65536);
        bulk_g2s(ubase, g_uh + (size_t)cbeg * 16384, 65536, mb);
    }

    for (int c = cbeg; c < cend; c++) {
        const int idx = c - cbeg;
        const int par = idx & 1;
        mbar_wait(mb, idx & 1);          // tile for c landed in buf[par]
        __syncthreads();                 // everyone done with buf[par^1]
        if (tid == 0 && c + 1 < cend) {
            mbar_expect(mb, 65536);
            bulk_g2s(ubase + (par ^ 1) * 65536,
                     g_uh + (size_t)(c + 1) * 16384, 65536, mb);
        }

        float bprev = (PASS == 2) ? g_b[c * U_DIM + lane] : 0.f;
        const u32 ub0 = ubase + par * 65536 + ((wb * 16) * 512 + ud) * 4;
        const u32* vb = g_vh + (wb * 16) * 512 + ud;
        float dp = 0.f;

#pragma unroll
        for (int t = 0; t < 16; t++) {
            u32 uh = lds_u32(ub0 + t * 2048);
            u32 vh = ldg_u32(vb + t * 512);
            float2 uu = __half22float2(*(__half2*)&uh);
            float2 vv = __half22float2(*(__half2*)&vh);
            dp = fmaf(uu.x, vv.x, dp);
            dp = fmaf(uu.y, vv.y, dp);
        }

        // reduce dp over d (16-lane segments); lanes 0/16 hold u partials
#pragma unroll
        for (int off = 8; off; off >>= 1)
            dp += __shfl_down_sync(0xffffffffu, dp, off, 16);
        if ((lane & 15) == 0) {
            float* rr = &red_sm[wb][wu * 2 + hw];
            *rr = dp;
        }
        __syncthreads();                 // red_sm ready

        // redundant per-warp softmax over u (lane = u)
        float dv = red_sm[0][lane] + red_sm[1][lane];
        float bv = dv * (1.0f / 64.0f) + bprev;
        if (PASS == 1 && w == 0) g_b[c * U_DIM + lane] = bv;
        float m = bv;
#pragma unroll
        for (int off = 16; off; off >>= 1)
            m = fmaxf(m, __shfl_xor_sync(0xffffffffu, m, off));
        float e = __expf(bv - m);
        float ssum = e;
#pragma unroll
        for (int off = 16; off; off >>= 1)
            ssum += __shfl_xor_sync(0xffffffffu, ssum, off);
        float cij = __shfl_sync(0xffffffffu, e / ssum, wu * 2 + hw);

        // phase B: s += cij * u_hat (re-read the smem tile)
#pragma unroll
        for (int t = 0; t < 16; t++) {
            u32 uh = lds_u32(ub0 + t * 2048);
            float2 uu = __half22float2(*(__half2*)&uh);
            sacc[2 * t]     = fmaf(cij, uu.x, sacc[2 * t]);
            sacc[2 * t + 1] = fmaf(cij, uu.y, sacc[2 * t + 1]);
        }
    }

    float* sp = g_spart + (size_t)blockIdx.x * (B_DIM * UD) + ud;
#pragma unroll
    for (int r = 0; r < 32; r++)
        sp[(wb * 32 + r) * UD] = sacc[r];
}

// Reduce per-block s partials (float4, 8-way p-split), apply squash
// (mag over U axis — reference quirk). 1024 threads.
__global__ void k_redsquash(float* __restrict__ dout, int final_out) {
    __shared__ float4 part[8][128];
    __shared__ float sq[UD];
    __shared__ float rs[D_DIM];
    const int b   = blockIdx.x;
    const int tid = threadIdx.x;
    const int ph  = tid >> 7;
    const int j   = tid & 127;

    const float4* sp = ((const float4*)g_spart) + b * 128 + j;
    float4 a = make_float4(0.f, 0.f, 0.f, 0.f);
    for (int p = ph; p < NBLK; p += 8) {
        float4 t = sp[p * 8192];
        a.x += t.x; a.y += t.y; a.z += t.z; a.w += t.w;
    }
    part[ph][j] = a;
    __syncthreads();

    float4 s4 = make_float4(0.f, 0.f, 0.f, 0.f);
    if (ph == 0) {
#pragma unroll
        for (int q = 0; q < 8; q++) {
            float4 t = part[q][j];
            s4.x += t.x; s4.y += t.y; s4.z += t.z; s4.w += t.w;
        }
        sq[4 * j]     = s4.x * s4.x;
        sq[4 * j + 1] = s4.y * s4.y;
        sq[4 * j + 2] = s4.z * s4.z;
        sq[4 * j + 3] = s4.w * s4.w;
    }
    __syncthreads();
    if (tid < D_DIM) {
        float msq = 0.f;
#pragma unroll
        for (int u = 0; u < U_DIM; u++) msq += sq[u * D_DIM + tid];
        rs[tid] = sqrtf(msq) / (1.0f + msq);   // mag_sq/((1+mag_sq)*mag)
    }
    __syncthreads();
    if (ph == 0) {
        const int ud = 4 * j;
        float o0 = s4.x * rs[ud & 15];
        float o1 = s4.y * rs[(ud + 1) & 15];
        float o2 = s4.z * rs[(ud + 2) & 15];
        float o3 = s4.w * rs[(ud + 3) & 15];
        if (final_out) {
            ((float4*)dout)[b * 128 + j] = make_float4(o0, o1, o2, o3);
        } else {
            // v as half in paired layout g_vh[b/2][ud] (lo=even b, hi=odd b)
            __half* vh = (__half*)g_vh;
            const int base = (b >> 1) * (UD * 2) + ud * 2 + (b & 1);
            vh[base]     = __float2half_rn(o0);
            vh[base + 2] = __float2half_rn(o1);
            vh[base + 4] = __float2half_rn(o2);
            vh[base + 6] = __float2half_rn(o3);
        }
    }
}

extern "C" void kernel_launch(void* const* d_in, const int* in_sizes, int n_in,
                              void* d_out, int out_size) {
    const float* x = (const float*)d_in[0];
    const float* W = (const float*)d_in[1];
    if (n_in >= 2 && in_sizes[0] == C_DIM * U_DIM * D_DIM * I_DIM) {
        const float* t = x; x = W; W = t;
    }
    float* out = (float*)d_out;

    const int SM0 = 32768 + 4096;     // k_einsum: W/x double buffers
    const int SM1 = 2 * 65536;        // k_route: u_hat double buffer
    cudaFuncSetAttribute(k_einsum,   cudaFuncAttributeMaxDynamicSharedMemorySize, SM0);
    cudaFuncSetAttribute(k_route<1>, cudaFuncAttributeMaxDynamicSharedMemorySize, SM1);
    cudaFuncSetAttribute(k_route<2>, cudaFuncAttributeMaxDynamicSharedMemorySize, SM1);

    k_transpose<<<(C_DIM * B_DIM * I_DIM + 255) / 256, 256>>>(x);

    // iteration 1: einsum -> u_hat(fp16) + s1 -> v1
    k_einsum<<<NBLK, NTH, SM0>>>(W);
    k_redsquash<<<B_DIM, NTH>>>(out, 0);

    // iteration 2: stream u_hat: delta(v1), b = delta, softmax -> s2 -> v2
    k_route<1><<<NBLK, NTH, SM1>>>();
    k_redsquash<<<B_DIM, NTH>>>(out, 0);

    // iteration 3: stream u_hat: delta(v2), b += delta, softmax -> s3 -> v3
    k_route<2><<<NBLK, NTH, SM1>>>();
    k_redsquash<<<B_DIM, NTH>>>(out, 1);
}